// round 9
// baseline (speedup 1.0000x reference)
#include <cuda_runtime.h>
#include <cuda_bf16.h>
#include <cstdint>

// kmeans assignment: tensor path via mma.sync (bf16 3-term split, fp32 acc)
// + exact-R6-chain rescue for near-ties -> output bit-identical to the
// passing R6 scalar kernel. Scalar R6 kernels retained as shape fallback.
//
// mm ~= xh.ph + xh.pl + xl.ph  (|err| << MARGIN/2)
// s_t = (x2 + p2) - 2*mm_t  with x2,p2 from the exact fp32 chain.
// candidates = { c : s_t < min(s_t) + MARGIN }  always contains the exact
// argmin; single candidate -> done, else recompute candidates exactly.

#define DD      50
#define CC_TC   256
#define TILE_M  128
#define PITCH_W 36              // words/row: banks 4r+j -> conflict-free
#define MARGIN  0.02f
#define FLT_BIG 3.402823466e38f
#define MAXD    128

// smem byte offsets (dynamic)
#define SM_XF  0
#define SM_X2  (SM_XF + TILE_M * DD * 4)            // 25600
#define SM_P2  (SM_X2 + TILE_M * 4)                 // 26112
#define SM_CNT (SM_P2 + CC_TC * 4)                  // 27136
#define SM_LST (SM_CNT + TILE_M * 4)                // 27648
#define SM_AH  (SM_LST + TILE_M * 8 * 4)            // 31744
#define SM_AL  (SM_AH + TILE_M * PITCH_W * 4)       // 50176
#define SM_BH  (SM_AL + TILE_M * PITCH_W * 4)       // 68608
#define SM_BL  (SM_BH + CC_TC * PITCH_W * 4)        // 105472
#define SM_TOT (SM_BL + CC_TC * PITCH_W * 4)        // 142336

__device__ __forceinline__ void mma16816(float* d, uint32_t a0, uint32_t a1,
                                         uint32_t a2, uint32_t a3,
                                         uint32_t b0, uint32_t b1) {
    asm volatile(
        "mma.sync.aligned.m16n8k16.row.col.f32.bf16.bf16.f32 "
        "{%0,%1,%2,%3}, {%4,%5,%6,%7}, {%8,%9}, {%0,%1,%2,%3};"
        : "+f"(d[0]), "+f"(d[1]), "+f"(d[2]), "+f"(d[3])
        : "r"(a0), "r"(a1), "r"(a2), "r"(a3), "r"(b0), "r"(b1));
}

__global__ __launch_bounds__(256, 1)
void kmeans_tc(const float* __restrict__ X,
               const float* __restrict__ Phi,
               float* __restrict__ out, int n)
{
    extern __shared__ char smem[];
    const int tid  = threadIdx.x;
    const int w    = tid >> 5;
    const int lane = tid & 31;
    const int rl   = lane >> 2;     // row-in-tile / n-in-tile selector
    const int jj   = lane & 3;      // k-pair selector

    float*          sXf = reinterpret_cast<float*>(smem + SM_XF);
    float*          sX2 = reinterpret_cast<float*>(smem + SM_X2);
    float*          sP2 = reinterpret_cast<float*>(smem + SM_P2);
    int*            sCn = reinterpret_cast<int*>(smem + SM_CNT);
    int*            sLs = reinterpret_cast<int*>(smem + SM_LST);
    __nv_bfloat16*  sAh = reinterpret_cast<__nv_bfloat16*>(smem + SM_AH);
    __nv_bfloat16*  sAl = reinterpret_cast<__nv_bfloat16*>(smem + SM_AL);
    __nv_bfloat16*  sBh = reinterpret_cast<__nv_bfloat16*>(smem + SM_BH);
    __nv_bfloat16*  sBl = reinterpret_cast<__nv_bfloat16*>(smem + SM_BL);

    // ---- phase 1: zero bf16 tiles (covers K-pad cols 50..63) + counters
    {
        uint4 z = make_uint4(0, 0, 0, 0);
        uint4* p = reinterpret_cast<uint4*>(smem + SM_AH);
        const int nw = (SM_TOT - SM_AH) / 16;
        for (int i = tid; i < nw; i += 256) p[i] = z;
        for (int i = tid; i < TILE_M; i += 256) sCn[i] = 0;
    }
    __syncthreads();

    const int gbase = blockIdx.x * TILE_M;

    // ---- phase 2: X tile -> fp32 smem + bf16 hi/lo fragments
    for (int idx = tid; idx < TILE_M * DD; idx += 256) {
        const int r = idx / DD, d = idx - r * DD;
        int pt = gbase + r; if (pt >= n) pt = n - 1;
        const float v = X[(long long)pt * DD + d];
        sXf[idx] = v;
        const __nv_bfloat16 h = __float2bfloat16(v);
        const __nv_bfloat16 l = __float2bfloat16(v - __bfloat162float(h));
        sAh[r * (PITCH_W * 2) + d] = h;
        sAl[r * (PITCH_W * 2) + d] = l;
    }
    // ---- phase 3: Phi -> bf16 hi/lo fragments
    for (int idx = tid; idx < CC_TC * DD; idx += 256) {
        const int c = idx / DD, d = idx - c * DD;
        const float v = Phi[idx];
        const __nv_bfloat16 h = __float2bfloat16(v);
        const __nv_bfloat16 l = __float2bfloat16(v - __bfloat162float(h));
        sBh[c * (PITCH_W * 2) + d] = h;
        sBl[c * (PITCH_W * 2) + d] = l;
    }
    __syncthreads();

    // ---- phase 4: exact-chain x2 (per point) and p2 (per centroid)
    if (tid < TILE_M) {
        const float* xr = sXf + tid * DD;
        float s = 0.f;
        #pragma unroll
        for (int d = 0; d < DD; ++d) s = __fadd_rn(s, __fmul_rn(xr[d], xr[d]));
        sX2[tid] = s;
    }
    {
        const int c = tid;  // 256 threads == 256 centroids
        float s = 0.f;
        #pragma unroll
        for (int d = 0; d < DD; ++d) {
            const float v = Phi[c * DD + d];
            s = __fadd_rn(s, __fmul_rn(v, v));
        }
        sP2[c] = s;
    }
    __syncthreads();

    // ---- phase 5: mma main loop (3 terms x 4 k16-steps x 32 n-tiles)
    float acc[128];
    #pragma unroll
    for (int i = 0; i < 128; ++i) acc[i] = 0.f;

    const uint32_t* Ah = reinterpret_cast<const uint32_t*>(sAh);
    const uint32_t* Al = reinterpret_cast<const uint32_t*>(sAl);
    const uint32_t* Bh = reinterpret_cast<const uint32_t*>(sBh);
    const uint32_t* Bl = reinterpret_cast<const uint32_t*>(sBl);
    const int arow = w * 16 + rl;

    #pragma unroll 1
    for (int term = 0; term < 3; ++term) {
        const uint32_t* A = (term == 2) ? Al : Ah;
        const uint32_t* B = (term == 1) ? Bl : Bh;
        #pragma unroll 1
        for (int ks = 0; ks < 4; ++ks) {
            const int ab = ks * 8 + jj;
            const uint32_t a0 = A[arow * PITCH_W + ab];
            const uint32_t a1 = A[(arow + 8) * PITCH_W + ab];
            const uint32_t a2 = A[arow * PITCH_W + ab + 4];
            const uint32_t a3 = A[(arow + 8) * PITCH_W + ab + 4];
            #pragma unroll
            for (int t = 0; t < 32; ++t) {
                const int brow = t * 8 + rl;
                const uint32_t b0 = B[brow * PITCH_W + ab];
                const uint32_t b1 = B[brow * PITCH_W + ab + 4];
                mma16816(acc + t * 4, a0, a1, a2, a3, b0, b1);
            }
        }
    }

    // ---- phase 6: epilogue
    const int row0 = w * 16 + rl;
    const int row1 = row0 + 8;
    const float x20 = sX2[row0];
    const float x21 = sX2[row1];

    // pass 1: per-thread min over owned (2 rows x 64 cols), quad-reduce
    float mn0 = FLT_BIG, mn1 = FLT_BIG;
    #pragma unroll
    for (int t = 0; t < 32; ++t) {
        const int c0 = t * 8 + 2 * jj;
        const float p0 = sP2[c0], p1 = sP2[c0 + 1];
        const float s00 = __fsub_rn(__fadd_rn(x20, p0), __fmul_rn(2.f, acc[t*4+0]));
        const float s01 = __fsub_rn(__fadd_rn(x20, p1), __fmul_rn(2.f, acc[t*4+1]));
        const float s10 = __fsub_rn(__fadd_rn(x21, p0), __fmul_rn(2.f, acc[t*4+2]));
        const float s11 = __fsub_rn(__fadd_rn(x21, p1), __fmul_rn(2.f, acc[t*4+3]));
        mn0 = fminf(mn0, fminf(s00, s01));
        mn1 = fminf(mn1, fminf(s10, s11));
    }
    mn0 = fminf(mn0, __shfl_xor_sync(0xFFFFFFFF, mn0, 1));
    mn0 = fminf(mn0, __shfl_xor_sync(0xFFFFFFFF, mn0, 2));
    mn1 = fminf(mn1, __shfl_xor_sync(0xFFFFFFFF, mn1, 1));
    mn1 = fminf(mn1, __shfl_xor_sync(0xFFFFFFFF, mn1, 2));
    const float thr0 = mn0 + MARGIN;
    const float thr1 = mn1 + MARGIN;

    // pass 2: collect candidates (smem atomics; lists per row)
    #pragma unroll
    for (int t = 0; t < 32; ++t) {
        const int c0 = t * 8 + 2 * jj;
        const float p0 = sP2[c0], p1 = sP2[c0 + 1];
        const float s00 = __fsub_rn(__fadd_rn(x20, p0), __fmul_rn(2.f, acc[t*4+0]));
        const float s01 = __fsub_rn(__fadd_rn(x20, p1), __fmul_rn(2.f, acc[t*4+1]));
        const float s10 = __fsub_rn(__fadd_rn(x21, p0), __fmul_rn(2.f, acc[t*4+2]));
        const float s11 = __fsub_rn(__fadd_rn(x21, p1), __fmul_rn(2.f, acc[t*4+3]));
        if (s00 < thr0) { int p = atomicAdd(&sCn[row0], 1); if (p < 8) sLs[row0*8+p] = c0;     }
        if (s01 < thr0) { int p = atomicAdd(&sCn[row0], 1); if (p < 8) sLs[row0*8+p] = c0 + 1; }
        if (s10 < thr1) { int p = atomicAdd(&sCn[row1], 1); if (p < 8) sLs[row1*8+p] = c0;     }
        if (s11 < thr1) { int p = atomicAdd(&sCn[row1], 1); if (p < 8) sLs[row1*8+p] = c0 + 1; }
    }
    __syncwarp();

    // owners (jj==0) resolve rows row0 and row1 with the exact R6 chain
    if (jj == 0) {
        #pragma unroll
        for (int rr = 0; rr < 2; ++rr) {
            const int row = rr ? row1 : row0;
            const float x2 = rr ? x21 : x20;
            const int cnt = sCn[row];
            int pick;
            if (cnt == 1) {
                pick = sLs[row * 8];
            } else if (cnt <= 8) {
                const float* xr = sXf + row * DD;
                float bs = FLT_BIG; int bc = CC_TC;
                for (int i = 0; i < cnt; ++i) {
                    const int c = sLs[row * 8 + i];
                    float mm = 0.f;
                    #pragma unroll
                    for (int d = 0; d < DD; ++d)
                        mm = __fmaf_rn(xr[d], __ldg(&Phi[c * DD + d]), mm);
                    const float s = __fsub_rn(__fadd_rn(x2, sP2[c]),
                                              __fmul_rn(2.f, mm));
                    if (s < bs || (s == bs && c < bc)) { bs = s; bc = c; }
                }
                pick = bc;
            } else {            // truncated list: full exact scan (rare)
                const float* xr = sXf + row * DD;
                float bs = FLT_BIG; pick = 0;
                for (int c = 0; c < CC_TC; ++c) {
                    float mm = 0.f;
                    #pragma unroll
                    for (int d = 0; d < DD; ++d)
                        mm = __fmaf_rn(xr[d], __ldg(&Phi[c * DD + d]), mm);
                    const float s = __fsub_rn(__fadd_rn(x2, sP2[c]),
                                              __fmul_rn(2.f, mm));
                    if (s < bs) { bs = s; pick = c; }
                }
            }
            if (gbase + row < n) out[gbase + row] = (float)pick;
        }
    }
}

// --------------------- R6 scalar fallback (D==50, any C) ---------------------
#define TPB   384
#define CHUNK 128
#define PPT   2
#define PTS_PER_BLOCK (TPB * PPT)

__global__ __launch_bounds__(TPB)
void kmeans_fast50(const float* __restrict__ X,
                   const float* __restrict__ Phi,
                   float* __restrict__ out, int n, int C)
{
    __shared__ __align__(16) float sPhiT[DD * CHUNK];
    __shared__ float sP2[CHUNK];

    const int base = blockIdx.x * PTS_PER_BLOCK;
    const int pt0  = base + threadIdx.x;
    const int pt1  = pt0 + TPB;

    float x0[DD], x1[DD];
    {
        const long long r0 = (long long)(pt0 < n ? pt0 : 0) * DD;
        const long long r1 = (long long)(pt1 < n ? pt1 : 0) * DD;
        const float2* a = reinterpret_cast<const float2*>(X + r0);
        const float2* b = reinterpret_cast<const float2*>(X + r1);
        #pragma unroll
        for (int j = 0; j < DD / 2; ++j) {
            float2 va = a[j]; x0[2*j] = va.x; x0[2*j+1] = va.y;
            float2 vb = b[j]; x1[2*j] = vb.x; x1[2*j+1] = vb.y;
        }
    }
    float x2a = 0.f, x2b = 0.f;
    #pragma unroll
    for (int d = 0; d < DD; ++d) {
        x2a = __fadd_rn(x2a, __fmul_rn(x0[d], x0[d]));
        x2b = __fadd_rn(x2b, __fmul_rn(x1[d], x1[d]));
    }

    float best0 = FLT_BIG, best1 = FLT_BIG;
    int   bi0 = 0, bi1 = 0;

    #pragma unroll 1
    for (int cb = 0; cb < C; cb += CHUNK) {
        const int cc = (C - cb < CHUNK) ? (C - cb) : CHUNK;
        __syncthreads();
        for (int i = threadIdx.x; i < cc * DD; i += TPB) {
            const int c = i / DD, d = i - c * DD;
            sPhiT[d * CHUNK + c] = Phi[(long long)(cb + c) * DD + d];
        }
        __syncthreads();
        if (threadIdx.x < cc) {
            float s = 0.f;
            #pragma unroll
            for (int d = 0; d < DD; ++d) {
                const float v = sPhiT[d * CHUNK + threadIdx.x];
                s = __fadd_rn(s, __fmul_rn(v, v));
            }
            sP2[threadIdx.x] = s;
        }
        __syncthreads();

        int c = 0;
        #pragma unroll 1
        for (; c + 4 <= cc; c += 4) {
            float a00=0.f,a01=0.f,a02=0.f,a03=0.f,a10=0.f,a11=0.f,a12=0.f,a13=0.f;
            const float4* pT = reinterpret_cast<const float4*>(sPhiT + c);
            #pragma unroll
            for (int d = 0; d < DD; ++d) {
                const float4 p = pT[d * (CHUNK / 4)];
                a00 = __fmaf_rn(x0[d], p.x, a00);
                a01 = __fmaf_rn(x0[d], p.y, a01);
                a02 = __fmaf_rn(x0[d], p.z, a02);
                a03 = __fmaf_rn(x0[d], p.w, a03);
                a10 = __fmaf_rn(x1[d], p.x, a10);
                a11 = __fmaf_rn(x1[d], p.y, a11);
                a12 = __fmaf_rn(x1[d], p.z, a12);
                a13 = __fmaf_rn(x1[d], p.w, a13);
            }
            const float q0=sP2[c],q1=sP2[c+1],q2=sP2[c+2],q3=sP2[c+3];
            const float s00=__fsub_rn(__fadd_rn(x2a,q0),__fmul_rn(2.f,a00));
            const float s01=__fsub_rn(__fadd_rn(x2a,q1),__fmul_rn(2.f,a01));
            const float s02=__fsub_rn(__fadd_rn(x2a,q2),__fmul_rn(2.f,a02));
            const float s03=__fsub_rn(__fadd_rn(x2a,q3),__fmul_rn(2.f,a03));
            const float s10=__fsub_rn(__fadd_rn(x2b,q0),__fmul_rn(2.f,a10));
            const float s11=__fsub_rn(__fadd_rn(x2b,q1),__fmul_rn(2.f,a11));
            const float s12=__fsub_rn(__fadd_rn(x2b,q2),__fmul_rn(2.f,a12));
            const float s13=__fsub_rn(__fadd_rn(x2b,q3),__fmul_rn(2.f,a13));
            const int g = cb + c;
            if (s00<best0){best0=s00;bi0=g;}   if (s01<best0){best0=s01;bi0=g+1;}
            if (s02<best0){best0=s02;bi0=g+2;} if (s03<best0){best0=s03;bi0=g+3;}
            if (s10<best1){best1=s10;bi1=g;}   if (s11<best1){best1=s11;bi1=g+1;}
            if (s12<best1){best1=s12;bi1=g+2;} if (s13<best1){best1=s13;bi1=g+3;}
        }
        for (; c < cc; ++c) {
            float a0=0.f,a1=0.f;
            #pragma unroll
            for (int d = 0; d < DD; ++d) {
                const float p = sPhiT[d * CHUNK + c];
                a0=__fmaf_rn(x0[d],p,a0); a1=__fmaf_rn(x1[d],p,a1);
            }
            const float q = sP2[c];
            const float s0=__fsub_rn(__fadd_rn(x2a,q),__fmul_rn(2.f,a0));
            const float s1=__fsub_rn(__fadd_rn(x2b,q),__fmul_rn(2.f,a1));
            if (s0<best0){best0=s0;bi0=cb+c;}
            if (s1<best1){best1=s1;bi1=cb+c;}
        }
    }
    if (pt0 < n) out[pt0] = (float)bi0;
    if (pt1 < n) out[pt1] = (float)bi1;
}

// --------------------- generic fallback: any D, C ---------------------
__global__ __launch_bounds__(256)
void kmeans_generic(const float* __restrict__ X,
                    const float* __restrict__ Phi,
                    float* __restrict__ out, int n, int D, int C)
{
    for (int idx = blockIdx.x * blockDim.x + threadIdx.x; idx < n;
         idx += gridDim.x * blockDim.x) {
        float xr[MAXD];
        const int Dc = (D < MAXD) ? D : MAXD;
        const long long row = (long long)idx * D;
        for (int d = 0; d < Dc; ++d) xr[d] = X[row + d];
        float x2 = 0.f;
        for (int d = 0; d < Dc; ++d) x2 = __fadd_rn(x2, __fmul_rn(xr[d], xr[d]));
        float best = FLT_BIG; int bi = 0;
        for (int c = 0; c < C; ++c) {
            const long long pr = (long long)c * D;
            float mm = 0.f, p2 = 0.f;
            for (int d = 0; d < Dc; ++d) {
                const float pv = __ldg(&Phi[pr + d]);
                mm = __fmaf_rn(xr[d], pv, mm);
                p2 = __fadd_rn(p2, __fmul_rn(pv, pv));
            }
            const float s = __fsub_rn(__fadd_rn(x2, p2), __fmul_rn(2.f, mm));
            if (s < best) { best = s; bi = c; }
        }
        out[idx] = (float)bi;
    }
}

// ------------------------------ launch ------------------------------
extern "C" void kernel_launch(void* const* d_in, const int* in_sizes, int n_in,
                              void* d_out, int out_size)
{
    int iX = 0;
    for (int i = 1; i < n_in; ++i)
        if (in_sizes[i] > in_sizes[iX]) iX = i;
    int iP = (iX == 0) ? (n_in > 1 ? 1 : 0) : 0;
    for (int i = 0; i < n_in; ++i)
        if (i != iX && in_sizes[i] > in_sizes[iP]) iP = i;

    const float* X   = (const float*)d_in[iX];
    const float* Phi = (const float*)d_in[iP];
    float*       out = (float*)d_out;

    const int n = out_size;
    if (n <= 0) return;
    const int D = in_sizes[iX] / n;
    const int C = (D > 0) ? in_sizes[iP] / D : 0;
    if (D <= 0 || C <= 0) return;

    if (D == DD && C == CC_TC) {
        cudaFuncSetAttribute(kmeans_tc,
                             cudaFuncAttributeMaxDynamicSharedMemorySize, SM_TOT);
        const int blocks = (n + TILE_M - 1) / TILE_M;
        kmeans_tc<<<blocks, 256, SM_TOT>>>(X, Phi, out, n);
    } else if (D == DD) {
        const int blocks = (n + PTS_PER_BLOCK - 1) / PTS_PER_BLOCK;
        kmeans_fast50<<<blocks, TPB>>>(X, Phi, out, n, C);
    } else {
        int blocks = (n + 255) / 256;
        if (blocks > 65535 * 8) blocks = 65535 * 8;
        kmeans_generic<<<blocks, 256>>>(X, Phi, out, n, D, C);
    }
}

// round 10
// speedup vs baseline: 1.6761x; 1.6761x over previous
#include <cuda_runtime.h>
#include <cuda_bf16.h>
#include <cstdint>

// kmeans assignment: persistent-CTA mma.sync bf16 3-term split + exact-chain
// rescue (output bit-identical to the R6 scalar chain).
//  - Phi bf16 hi/lo + p2 precomputed ONCE into __device__ globals
//  - each CTA loads B fragments to smem once, then loops over point tiles
//  - X tiles double-buffered via cp.async, overlapped with mma+epilogue

#define DD      50
#define CC_TC   256
#define TILE_M  128
#define KPAD    64
#define PITCH_W 36              // words/row -> conflict-free quads
#define MARGIN  0.02f
#define FLT_BIG 3.402823466e38f
#define MAXD    128
#define NSM     152

// smem byte offsets (dynamic)
#define SM_X0   0
#define SM_X1   (SM_X0 + TILE_M * DD * 4)           // 25600
#define SM_X2V  (SM_X1 + TILE_M * DD * 4)           // 51200
#define SM_P2   (SM_X2V + TILE_M * 4)               // 51712
#define SM_CNT  (SM_P2 + CC_TC * 4)                 // 52736
#define SM_LST  (SM_CNT + TILE_M * 4)               // 53248
#define SM_AH   (SM_LST + TILE_M * 8 * 4)           // 57344
#define SM_AL   (SM_AH + TILE_M * PITCH_W * 4)      // 75776
#define SM_BH   (SM_AL + TILE_M * PITCH_W * 4)      // 94208
#define SM_BL   (SM_BH + CC_TC * PITCH_W * 4)       // 131072
#define SM_TOT  (SM_BL + CC_TC * PITCH_W * 4)       // 167936

__device__ __align__(16) __nv_bfloat16 gPhiH[CC_TC * KPAD];
__device__ __align__(16) __nv_bfloat16 gPhiL[CC_TC * KPAD];
__device__ float gP2[CC_TC];

__global__ void prep_kernel(const float* __restrict__ Phi)
{
    const int c = threadIdx.x;                 // 256 threads == 256 centroids
    float s = 0.f;
    for (int d = 0; d < KPAD; ++d) {
        __nv_bfloat16 h = __float2bfloat16(0.f);
        __nv_bfloat16 l = h;
        if (d < DD) {
            const float v = Phi[c * DD + d];
            h = __float2bfloat16(v);
            l = __float2bfloat16(v - __bfloat162float(h));
            s = __fadd_rn(s, __fmul_rn(v, v));  // exact R6 chain
        }
        gPhiH[c * KPAD + d] = h;
        gPhiL[c * KPAD + d] = l;
    }
    gP2[c] = s;
}

__device__ __forceinline__ uint32_t smem_u32(const void* p) {
    uint32_t a;
    asm("{ .reg .u64 t; cvta.to.shared.u64 t, %1; cvt.u32.u64 %0, t; }"
        : "=r"(a) : "l"(p));
    return a;
}
__device__ __forceinline__ void cp16(uint32_t saddr, const void* g) {
    asm volatile("cp.async.ca.shared.global [%0], [%1], 16;"
                 :: "r"(saddr), "l"(g));
}
__device__ __forceinline__ void mma16816(float* d, uint32_t a0, uint32_t a1,
                                         uint32_t a2, uint32_t a3,
                                         uint32_t b0, uint32_t b1) {
    asm volatile(
        "mma.sync.aligned.m16n8k16.row.col.f32.bf16.bf16.f32 "
        "{%0,%1,%2,%3}, {%4,%5,%6,%7}, {%8,%9}, {%0,%1,%2,%3};"
        : "+f"(d[0]), "+f"(d[1]), "+f"(d[2]), "+f"(d[3])
        : "r"(a0), "r"(a1), "r"(a2), "r"(a3), "r"(b0), "r"(b1));
}

__global__ __launch_bounds__(256, 1)
void kmeans_tc(const float* __restrict__ X,
               const float* __restrict__ Phi,
               float* __restrict__ out, int n, int ntiles)
{
    extern __shared__ char smem[];
    const int tid  = threadIdx.x;
    const int w    = tid >> 5;
    const int lane = tid & 31;
    const int rl   = lane >> 2;
    const int jj   = lane & 3;

    float*    sX2 = reinterpret_cast<float*>(smem + SM_X2V);
    float*    sP2 = reinterpret_cast<float*>(smem + SM_P2);
    int*      sCn = reinterpret_cast<int*>(smem + SM_CNT);
    int*      sLs = reinterpret_cast<int*>(smem + SM_LST);
    uint32_t* AhW = reinterpret_cast<uint32_t*>(smem + SM_AH);
    uint32_t* AlW = reinterpret_cast<uint32_t*>(smem + SM_AL);
    uint32_t* BhW = reinterpret_cast<uint32_t*>(smem + SM_BH);
    uint32_t* BlW = reinterpret_cast<uint32_t*>(smem + SM_BL);

    const uint32_t sx0 = smem_u32(smem + SM_X0);
    const uint32_t sx1 = smem_u32(smem + SM_X1);

    int  tile = blockIdx.x;
    int  buf  = 0;
    bool pref = false;

    // prefetch first tile ASAP (overlaps with B-fragment setup below)
    if (tile < ntiles) {
        const long long base = (long long)tile * TILE_M;
        if (base + TILE_M <= n) {
            const char* src = reinterpret_cast<const char*>(X + base * DD);
            for (int i = tid; i < TILE_M * DD * 4 / 16; i += 256)
                cp16(sx0 + i * 16, src + i * 16);
            pref = true;
        }
    }
    asm volatile("cp.async.commit_group;" ::: "memory");

    // one-time per CTA: B fragments (pitched), p2, zero A pad words 25..31
    {
        const uint32_t* gBH = reinterpret_cast<const uint32_t*>(gPhiH);
        const uint32_t* gBL = reinterpret_cast<const uint32_t*>(gPhiL);
        for (int i = tid; i < CC_TC * (KPAD / 2); i += 256) {
            const int r = i >> 5, q = i & 31;
            BhW[r * PITCH_W + q] = gBH[i];
            BlW[r * PITCH_W + q] = gBL[i];
        }
        if (tid < CC_TC) sP2[tid] = gP2[tid];
        for (int i = tid; i < TILE_M * 7 * 2; i += 256) {
            const int a = i / (TILE_M * 7);
            const int j = i - a * (TILE_M * 7);
            const int r = j / 7, q = 25 + (j - r * 7);
            (a ? AlW : AhW)[r * PITCH_W + q] = 0u;
        }
    }

    const int arow = w * 16 + rl;

    for (; tile < ntiles; tile += gridDim.x) {
        const long long gbase = (long long)tile * TILE_M;
        const bool full = (gbase + TILE_M <= n);

        if (pref) asm volatile("cp.async.wait_group 0;" ::: "memory");
        __syncthreads();   // prev iter fully done; cur X buffer published

        float* sXf = reinterpret_cast<float*>(smem + (buf ? SM_X1 : SM_X0));
        if (!full) {       // tail tile: direct clamped load (once globally)
            for (int idx = tid; idx < TILE_M * DD; idx += 256) {
                const int r = idx / DD, d = idx - r * DD;
                long long pt = gbase + r; if (pt >= n) pt = n - 1;
                sXf[idx] = X[pt * DD + d];
            }
            __syncthreads();
        }

        // convert X -> bf16 hi/lo fragments (pairs: one 32-bit STS each)
        for (int idx = tid; idx < TILE_M * 25; idx += 256) {
            const int r = idx / 25, p = idx - r * 25;
            const float2 v = *reinterpret_cast<const float2*>(sXf + r * DD + 2 * p);
            const __nv_bfloat16 h0 = __float2bfloat16(v.x);
            const __nv_bfloat16 h1 = __float2bfloat16(v.y);
            const __nv_bfloat16 l0 = __float2bfloat16(v.x - __bfloat162float(h0));
            const __nv_bfloat16 l1 = __float2bfloat16(v.y - __bfloat162float(h1));
            AhW[r * PITCH_W + p] = (uint32_t)__bfloat16_as_ushort(h0)
                                 | ((uint32_t)__bfloat16_as_ushort(h1) << 16);
            AlW[r * PITCH_W + p] = (uint32_t)__bfloat16_as_ushort(l0)
                                 | ((uint32_t)__bfloat16_as_ushort(l1) << 16);
        }
        if (tid < TILE_M) {           // exact-chain x2 + zero candidate count
            sCn[tid] = 0;
            const float* xr = sXf + tid * DD;
            float s = 0.f;
            #pragma unroll
            for (int d = 0; d < DD; ++d) s = __fadd_rn(s, __fmul_rn(xr[d], xr[d]));
            sX2[tid] = s;
        }
        __syncthreads();

        // prefetch next tile into the other buffer (overlaps mma+epilogue)
        {
            const int nt = tile + gridDim.x;
            pref = false;
            if (nt < ntiles) {
                const long long nb = (long long)nt * TILE_M;
                if (nb + TILE_M <= n) {
                    const char* src = reinterpret_cast<const char*>(X + nb * DD);
                    const uint32_t dst = buf ? sx0 : sx1;
                    for (int i = tid; i < TILE_M * DD * 4 / 16; i += 256)
                        cp16(dst + i * 16, src + i * 16);
                    pref = true;
                }
            }
            asm volatile("cp.async.commit_group;" ::: "memory");
        }

        // ---- mma: 3 terms x 4 k16-steps x 32 n-tiles
        float acc[128];
        #pragma unroll
        for (int i = 0; i < 128; ++i) acc[i] = 0.f;

        #pragma unroll 1
        for (int term = 0; term < 3; ++term) {
            const uint32_t* A = (term == 2) ? AlW : AhW;
            const uint32_t* B = (term == 1) ? BlW : BhW;
            #pragma unroll 1
            for (int ks = 0; ks < 4; ++ks) {
                const int ab = ks * 8 + jj;
                const uint32_t a0 = A[arow * PITCH_W + ab];
                const uint32_t a1 = A[(arow + 8) * PITCH_W + ab];
                const uint32_t a2 = A[arow * PITCH_W + ab + 4];
                const uint32_t a3 = A[(arow + 8) * PITCH_W + ab + 4];
                const uint32_t* Bp = B + rl * PITCH_W + ab;
                #pragma unroll
                for (int t = 0; t < 32; ++t) {
                    const uint32_t b0 = Bp[t * 8 * PITCH_W];
                    const uint32_t b1 = Bp[t * 8 * PITCH_W + 4];
                    mma16816(acc + t * 4, a0, a1, a2, a3, b0, b1);
                }
            }
        }

        // ---- epilogue (identical logic to validated R9)
        const int row0 = arow;
        const int row1 = arow + 8;
        const float x20 = sX2[row0];
        const float x21 = sX2[row1];

        float mn0 = FLT_BIG, mn1 = FLT_BIG;
        #pragma unroll
        for (int t = 0; t < 32; ++t) {
            const int c0 = t * 8 + 2 * jj;
            const float p0 = sP2[c0], p1 = sP2[c0 + 1];
            const float s00 = __fsub_rn(__fadd_rn(x20, p0), __fmul_rn(2.f, acc[t*4+0]));
            const float s01 = __fsub_rn(__fadd_rn(x20, p1), __fmul_rn(2.f, acc[t*4+1]));
            const float s10 = __fsub_rn(__fadd_rn(x21, p0), __fmul_rn(2.f, acc[t*4+2]));
            const float s11 = __fsub_rn(__fadd_rn(x21, p1), __fmul_rn(2.f, acc[t*4+3]));
            mn0 = fminf(mn0, fminf(s00, s01));
            mn1 = fminf(mn1, fminf(s10, s11));
        }
        mn0 = fminf(mn0, __shfl_xor_sync(0xFFFFFFFF, mn0, 1));
        mn0 = fminf(mn0, __shfl_xor_sync(0xFFFFFFFF, mn0, 2));
        mn1 = fminf(mn1, __shfl_xor_sync(0xFFFFFFFF, mn1, 1));
        mn1 = fminf(mn1, __shfl_xor_sync(0xFFFFFFFF, mn1, 2));
        const float thr0 = mn0 + MARGIN;
        const float thr1 = mn1 + MARGIN;

        #pragma unroll
        for (int t = 0; t < 32; ++t) {
            const int c0 = t * 8 + 2 * jj;
            const float p0 = sP2[c0], p1 = sP2[c0 + 1];
            const float s00 = __fsub_rn(__fadd_rn(x20, p0), __fmul_rn(2.f, acc[t*4+0]));
            const float s01 = __fsub_rn(__fadd_rn(x20, p1), __fmul_rn(2.f, acc[t*4+1]));
            const float s10 = __fsub_rn(__fadd_rn(x21, p0), __fmul_rn(2.f, acc[t*4+2]));
            const float s11 = __fsub_rn(__fadd_rn(x21, p1), __fmul_rn(2.f, acc[t*4+3]));
            if (s00 < thr0) { int p = atomicAdd(&sCn[row0], 1); if (p < 8) sLs[row0*8+p] = c0;     }
            if (s01 < thr0) { int p = atomicAdd(&sCn[row0], 1); if (p < 8) sLs[row0*8+p] = c0 + 1; }
            if (s10 < thr1) { int p = atomicAdd(&sCn[row1], 1); if (p < 8) sLs[row1*8+p] = c0;     }
            if (s11 < thr1) { int p = atomicAdd(&sCn[row1], 1); if (p < 8) sLs[row1*8+p] = c0 + 1; }
        }
        __syncwarp();

        if (jj == 0) {
            #pragma unroll
            for (int rr = 0; rr < 2; ++rr) {
                const int row = rr ? row1 : row0;
                const float x2 = rr ? x21 : x20;
                const int cnt = sCn[row];
                int pick;
                if (cnt == 1) {
                    pick = sLs[row * 8];     // provably the exact-chain argmin
                } else if (cnt <= 8) {
                    const float* xr = sXf + row * DD;
                    float bs = FLT_BIG; int bc = CC_TC;
                    for (int i = 0; i < cnt; ++i) {
                        const int c = sLs[row * 8 + i];
                        float mm = 0.f;
                        #pragma unroll
                        for (int d = 0; d < DD; ++d)
                            mm = __fmaf_rn(xr[d], __ldg(&Phi[c * DD + d]), mm);
                        const float s = __fsub_rn(__fadd_rn(x2, sP2[c]),
                                                  __fmul_rn(2.f, mm));
                        if (s < bs || (s == bs && c < bc)) { bs = s; bc = c; }
                    }
                    pick = bc;
                } else {                     // truncated list: full exact scan
                    const float* xr = sXf + row * DD;
                    float bs = FLT_BIG; pick = 0;
                    for (int c = 0; c < CC_TC; ++c) {
                        float mm = 0.f;
                        #pragma unroll
                        for (int d = 0; d < DD; ++d)
                            mm = __fmaf_rn(xr[d], __ldg(&Phi[c * DD + d]), mm);
                        const float s = __fsub_rn(__fadd_rn(x2, sP2[c]),
                                                  __fmul_rn(2.f, mm));
                        if (s < bs) { bs = s; pick = c; }
                    }
                }
                if (gbase + row < n) out[gbase + row] = (float)pick;
            }
        }
        buf ^= 1;
    }
}

// --------------------- R6 scalar fallback (D==50, any C) ---------------------
#define TPB   384
#define CHUNK 128
#define PPT   2
#define PTS_PER_BLOCK (TPB * PPT)

__global__ __launch_bounds__(TPB)
void kmeans_fast50(const float* __restrict__ X,
                   const float* __restrict__ Phi,
                   float* __restrict__ out, int n, int C)
{
    __shared__ __align__(16) float sPhiT[DD * CHUNK];
    __shared__ float sP2[CHUNK];

    const int base = blockIdx.x * PTS_PER_BLOCK;
    const int pt0  = base + threadIdx.x;
    const int pt1  = pt0 + TPB;

    float x0[DD], x1[DD];
    {
        const long long r0 = (long long)(pt0 < n ? pt0 : 0) * DD;
        const long long r1 = (long long)(pt1 < n ? pt1 : 0) * DD;
        const float2* a = reinterpret_cast<const float2*>(X + r0);
        const float2* b = reinterpret_cast<const float2*>(X + r1);
        #pragma unroll
        for (int j = 0; j < DD / 2; ++j) {
            float2 va = a[j]; x0[2*j] = va.x; x0[2*j+1] = va.y;
            float2 vb = b[j]; x1[2*j] = vb.x; x1[2*j+1] = vb.y;
        }
    }
    float x2a = 0.f, x2b = 0.f;
    #pragma unroll
    for (int d = 0; d < DD; ++d) {
        x2a = __fadd_rn(x2a, __fmul_rn(x0[d], x0[d]));
        x2b = __fadd_rn(x2b, __fmul_rn(x1[d], x1[d]));
    }

    float best0 = FLT_BIG, best1 = FLT_BIG;
    int   bi0 = 0, bi1 = 0;

    #pragma unroll 1
    for (int cb = 0; cb < C; cb += CHUNK) {
        const int cc = (C - cb < CHUNK) ? (C - cb) : CHUNK;
        __syncthreads();
        for (int i = threadIdx.x; i < cc * DD; i += TPB) {
            const int c = i / DD, d = i - c * DD;
            sPhiT[d * CHUNK + c] = Phi[(long long)(cb + c) * DD + d];
        }
        __syncthreads();
        if (threadIdx.x < cc) {
            float s = 0.f;
            #pragma unroll
            for (int d = 0; d < DD; ++d) {
                const float v = sPhiT[d * CHUNK + threadIdx.x];
                s = __fadd_rn(s, __fmul_rn(v, v));
            }
            sP2[threadIdx.x] = s;
        }
        __syncthreads();

        int c = 0;
        #pragma unroll 1
        for (; c + 4 <= cc; c += 4) {
            float a00=0.f,a01=0.f,a02=0.f,a03=0.f,a10=0.f,a11=0.f,a12=0.f,a13=0.f;
            const float4* pT = reinterpret_cast<const float4*>(sPhiT + c);
            #pragma unroll
            for (int d = 0; d < DD; ++d) {
                const float4 p = pT[d * (CHUNK / 4)];
                a00 = __fmaf_rn(x0[d], p.x, a00);
                a01 = __fmaf_rn(x0[d], p.y, a01);
                a02 = __fmaf_rn(x0[d], p.z, a02);
                a03 = __fmaf_rn(x0[d], p.w, a03);
                a10 = __fmaf_rn(x1[d], p.x, a10);
                a11 = __fmaf_rn(x1[d], p.y, a11);
                a12 = __fmaf_rn(x1[d], p.z, a12);
                a13 = __fmaf_rn(x1[d], p.w, a13);
            }
            const float q0=sP2[c],q1=sP2[c+1],q2=sP2[c+2],q3=sP2[c+3];
            const float s00=__fsub_rn(__fadd_rn(x2a,q0),__fmul_rn(2.f,a00));
            const float s01=__fsub_rn(__fadd_rn(x2a,q1),__fmul_rn(2.f,a01));
            const float s02=__fsub_rn(__fadd_rn(x2a,q2),__fmul_rn(2.f,a02));
            const float s03=__fsub_rn(__fadd_rn(x2a,q3),__fmul_rn(2.f,a03));
            const float s10=__fsub_rn(__fadd_rn(x2b,q0),__fmul_rn(2.f,a10));
            const float s11=__fsub_rn(__fadd_rn(x2b,q1),__fmul_rn(2.f,a11));
            const float s12=__fsub_rn(__fadd_rn(x2b,q2),__fmul_rn(2.f,a12));
            const float s13=__fsub_rn(__fadd_rn(x2b,q3),__fmul_rn(2.f,a13));
            const int g = cb + c;
            if (s00<best0){best0=s00;bi0=g;}   if (s01<best0){best0=s01;bi0=g+1;}
            if (s02<best0){best0=s02;bi0=g+2;} if (s03<best0){best0=s03;bi0=g+3;}
            if (s10<best1){best1=s10;bi1=g;}   if (s11<best1){best1=s11;bi1=g+1;}
            if (s12<best1){best1=s12;bi1=g+2;} if (s13<best1){best1=s13;bi1=g+3;}
        }
        for (; c < cc; ++c) {
            float a0=0.f,a1=0.f;
            #pragma unroll
            for (int d = 0; d < DD; ++d) {
                const float p = sPhiT[d * CHUNK + c];
                a0=__fmaf_rn(x0[d],p,a0); a1=__fmaf_rn(x1[d],p,a1);
            }
            const float q = sP2[c];
            const float s0=__fsub_rn(__fadd_rn(x2a,q),__fmul_rn(2.f,a0));
            const float s1=__fsub_rn(__fadd_rn(x2b,q),__fmul_rn(2.f,a1));
            if (s0<best0){best0=s0;bi0=cb+c;}
            if (s1<best1){best1=s1;bi1=cb+c;}
        }
    }
    if (pt0 < n) out[pt0] = (float)bi0;
    if (pt1 < n) out[pt1] = (float)bi1;
}

// --------------------- generic fallback: any D, C ---------------------
__global__ __launch_bounds__(256)
void kmeans_generic(const float* __restrict__ X,
                    const float* __restrict__ Phi,
                    float* __restrict__ out, int n, int D, int C)
{
    for (int idx = blockIdx.x * blockDim.x + threadIdx.x; idx < n;
         idx += gridDim.x * blockDim.x) {
        float xr[MAXD];
        const int Dc = (D < MAXD) ? D : MAXD;
        const long long row = (long long)idx * D;
        for (int d = 0; d < Dc; ++d) xr[d] = X[row + d];
        float x2 = 0.f;
        for (int d = 0; d < Dc; ++d) x2 = __fadd_rn(x2, __fmul_rn(xr[d], xr[d]));
        float best = FLT_BIG; int bi = 0;
        for (int c = 0; c < C; ++c) {
            const long long pr = (long long)c * D;
            float mm = 0.f, p2 = 0.f;
            for (int d = 0; d < Dc; ++d) {
                const float pv = __ldg(&Phi[pr + d]);
                mm = __fmaf_rn(xr[d], pv, mm);
                p2 = __fadd_rn(p2, __fmul_rn(pv, pv));
            }
            const float s = __fsub_rn(__fadd_rn(x2, p2), __fmul_rn(2.f, mm));
            if (s < best) { best = s; bi = c; }
        }
        out[idx] = (float)bi;
    }
}

// ------------------------------ launch ------------------------------
extern "C" void kernel_launch(void* const* d_in, const int* in_sizes, int n_in,
                              void* d_out, int out_size)
{
    int iX = 0;
    for (int i = 1; i < n_in; ++i)
        if (in_sizes[i] > in_sizes[iX]) iX = i;
    int iP = (iX == 0) ? (n_in > 1 ? 1 : 0) : 0;
    for (int i = 0; i < n_in; ++i)
        if (i != iX && in_sizes[i] > in_sizes[iP]) iP = i;

    const float* X   = (const float*)d_in[iX];
    const float* Phi = (const float*)d_in[iP];
    float*       out = (float*)d_out;

    const int n = out_size;
    if (n <= 0) return;
    const int D = in_sizes[iX] / n;
    const int C = (D > 0) ? in_sizes[iP] / D : 0;
    if (D <= 0 || C <= 0) return;

    if (D == DD && C == CC_TC) {
        prep_kernel<<<1, 256>>>(Phi);
        cudaFuncSetAttribute(kmeans_tc,
                             cudaFuncAttributeMaxDynamicSharedMemorySize, SM_TOT);
        const int ntiles = (n + TILE_M - 1) / TILE_M;
        const int grid = (ntiles < NSM) ? ntiles : NSM;
        kmeans_tc<<<grid, 256, SM_TOT>>>(X, Phi, out, n, ntiles);
    } else if (D == DD) {
        const int blocks = (n + PTS_PER_BLOCK - 1) / PTS_PER_BLOCK;
        kmeans_fast50<<<blocks, TPB>>>(X, Phi, out, n, C);
    } else {
        int blocks = (n + 255) / 256;
        if (blocks > 65535 * 8) blocks = 65535 * 8;
        kmeans_generic<<<blocks, 256>>>(X, Phi, out, n, D, C);
    }
}

// round 11
// speedup vs baseline: 2.0508x; 1.2236x over previous
#include <cuda_runtime.h>
#include <cuda_bf16.h>
#include <cstdint>

// kmeans assignment: persistent-CTA mma.sync bf16 3-term split + exact-chain
// rescue; output bit-identical to the R6 scalar chain (rel_err 9.9065e-4).
// R11: 512 threads (16 warps, acc[64] each, warp-pair splits the 256
// centroids), operands stored in mma-fragment-ordered u64 layout
// (B precomputed once, A converted per tile) -> 1 LDS.64 + 1 HMMA inner step.

#define DD      50
#define CC_TC   256
#define TILE_M  128
#define MARGIN  0.02f
#define FLT_BIG 3.402823466e38f
#define MAXD    128
#define NSM     152
#define TPBT    512

typedef unsigned long long u64;

// smem byte offsets (dynamic)
#define SM_X0   0
#define SM_X1   (SM_X0 + TILE_M * DD * 4)            // 25600
#define SM_X2V  (SM_X1 + TILE_M * DD * 4)            // 51200
#define SM_P2   (SM_X2V + TILE_M * 4)                // 51712
#define SM_CNT  (SM_P2 + CC_TC * 4)                  // 52736
#define SM_LST  (SM_CNT + TILE_M * 4)                // 53248
#define SM_PMIN (SM_LST + TILE_M * 8 * 4)            // 57344
#define SM_AH   (SM_PMIN + TILE_M * 2 * 4)           // 58368
#define SM_AL   (SM_AH + 4 * TILE_M * 4 * 8)         // 74752
#define SM_BF   (SM_AL + 4 * TILE_M * 4 * 8)         // 91136
#define SM_TOT  (SM_BF + 8 * CC_TC * 4 * 8)          // 156672

// B fragments in mma order: gBfrag[slot<8][c<256][jj<4] = (b0,b1)
// slots 0..3 = Bh ks 0..3, slots 4..7 = Bl ks 0..3
__device__ __align__(16) u64 gBfrag[8 * CC_TC * 4];
__device__ float gP2[CC_TC];

__global__ void prep_kernel(const float* __restrict__ Phi)
{
    const int c = threadIdx.x;                 // 256 threads == 256 centroids
    unsigned short h[64], l[64];
    float s = 0.f;
    for (int d = 0; d < 64; ++d) {
        if (d < DD) {
            const float v  = Phi[c * DD + d];
            const __nv_bfloat16 bh = __float2bfloat16(v);
            const __nv_bfloat16 bl = __float2bfloat16(v - __bfloat162float(bh));
            h[d] = __bfloat16_as_ushort(bh);
            l[d] = __bfloat16_as_ushort(bl);
            s = __fadd_rn(s, __fmul_rn(v, v));  // exact R6 chain
        } else { h[d] = 0; l[d] = 0; }
    }
    gP2[c] = s;
    for (int ks = 0; ks < 4; ++ks)
        for (int jj = 0; jj < 4; ++jj) {
            const int k0 = 16 * ks + 2 * jj;        // b0 elements
            const int k1 = 16 * ks + 8 + 2 * jj;    // b1 elements
            const u64 vh = (u64)((uint32_t)h[k0] | ((uint32_t)h[k0+1] << 16))
                         | ((u64)((uint32_t)h[k1] | ((uint32_t)h[k1+1] << 16)) << 32);
            const u64 vl = (u64)((uint32_t)l[k0] | ((uint32_t)l[k0+1] << 16))
                         | ((u64)((uint32_t)l[k1] | ((uint32_t)l[k1+1] << 16)) << 32);
            gBfrag[(ks * CC_TC + c) * 4 + jj]       = vh;
            gBfrag[((4 + ks) * CC_TC + c) * 4 + jj] = vl;
        }
}

__device__ __forceinline__ uint32_t smem_u32(const void* p) {
    uint32_t a;
    asm("{ .reg .u64 t; cvta.to.shared.u64 t, %1; cvt.u32.u64 %0, t; }"
        : "=r"(a) : "l"(p));
    return a;
}
__device__ __forceinline__ void cp16(uint32_t saddr, const void* g) {
    asm volatile("cp.async.ca.shared.global [%0], [%1], 16;"
                 :: "r"(saddr), "l"(g));
}
__device__ __forceinline__ void mma16816(float* d, uint32_t a0, uint32_t a1,
                                         uint32_t a2, uint32_t a3,
                                         uint32_t b0, uint32_t b1) {
    asm volatile(
        "mma.sync.aligned.m16n8k16.row.col.f32.bf16.bf16.f32 "
        "{%0,%1,%2,%3}, {%4,%5,%6,%7}, {%8,%9}, {%0,%1,%2,%3};"
        : "+f"(d[0]), "+f"(d[1]), "+f"(d[2]), "+f"(d[3])
        : "r"(a0), "r"(a1), "r"(a2), "r"(a3), "r"(b0), "r"(b1));
}
__device__ __forceinline__ void unpk(u64 v, uint32_t& lo, uint32_t& hi) {
    asm("mov.b64 {%0, %1}, %2;" : "=r"(lo), "=r"(hi) : "l"(v));
}

__global__ __launch_bounds__(TPBT, 1)
void kmeans_tc(const float* __restrict__ X,
               const float* __restrict__ Phi,
               float* __restrict__ out, int n, int ntiles)
{
    extern __shared__ char smem[];
    const int tid  = threadIdx.x;
    const int w    = tid >> 5;
    const int lane = tid & 31;
    const int rl   = lane >> 2;
    const int jj   = lane & 3;
    const int half = w & 1;              // which 128 centroids
    const int arow = (w >> 1) * 16 + rl; // A row stripe (16 rows/warp-pair)

    float*    sX2 = reinterpret_cast<float*>(smem + SM_X2V);
    float*    sP2 = reinterpret_cast<float*>(smem + SM_P2);
    int*      sCn = reinterpret_cast<int*>(smem + SM_CNT);
    int*      sLs = reinterpret_cast<int*>(smem + SM_LST);
    float*    sPm = reinterpret_cast<float*>(smem + SM_PMIN);   // [row][half]
    uint32_t* AhW = reinterpret_cast<uint32_t*>(smem + SM_AH);
    uint32_t* AlW = reinterpret_cast<uint32_t*>(smem + SM_AL);
    const u64* Ah64 = reinterpret_cast<const u64*>(smem + SM_AH);
    const u64* Al64 = reinterpret_cast<const u64*>(smem + SM_AL);
    u64*       Bf   = reinterpret_cast<u64*>(smem + SM_BF);

    const uint32_t sx0 = smem_u32(smem + SM_X0);
    const uint32_t sx1 = smem_u32(smem + SM_X1);

    int  tile = blockIdx.x;
    int  buf  = 0;
    bool pref = false;

    // prefetch first tile ASAP
    if (tile < ntiles) {
        const long long base = (long long)tile * TILE_M;
        if (base + TILE_M <= n) {
            const char* src = reinterpret_cast<const char*>(X + base * DD);
            for (int i = tid; i < TILE_M * DD * 4 / 16; i += TPBT)
                cp16(sx0 + i * 16, src + i * 16);
            pref = true;
        }
    }
    asm volatile("cp.async.commit_group;" ::: "memory");

    // one-time per CTA: copy B fragments + p2, zero A pad words (p=25..31)
    {
        const u64* g = gBfrag;
        for (int i = tid; i < 8 * CC_TC * 4; i += TPBT) Bf[i] = g[i];
        for (int i = tid; i < CC_TC; i += TPBT) sP2[i] = gP2[i];
        // pad words: ks=3, q=1..7 -> u32 idx = 3*1024 + r*8 + (q&3)*2+(q>>2)
        for (int i = tid; i < TILE_M * 7 * 2; i += TPBT) {
            const int a = i / (TILE_M * 7);
            const int j = i - a * (TILE_M * 7);
            const int r = j / 7, q = 1 + (j - r * 7);
            const int u = 3 * 1024 + r * 8 + (q & 3) * 2 + (q >> 2);
            (a ? AlW : AhW)[u] = 0u;
        }
    }

    for (; tile < ntiles; tile += gridDim.x) {
        const long long gbase = (long long)tile * TILE_M;
        const bool full = (gbase + TILE_M <= n);

        if (pref) asm volatile("cp.async.wait_group 0;" ::: "memory");
        __syncthreads();

        float* sXf = reinterpret_cast<float*>(smem + (buf ? SM_X1 : SM_X0));
        if (!full) {
            for (int idx = tid; idx < TILE_M * DD; idx += TPBT) {
                const int r = idx / DD, d = idx - r * DD;
                long long pt = gbase + r; if (pt >= n) pt = n - 1;
                sXf[idx] = X[pt * DD + d];
            }
            __syncthreads();
        }

        // convert X -> bf16 hi/lo, written in fragment-ordered u32 slots
        for (int idx = tid; idx < TILE_M * 25; idx += TPBT) {
            const int r = idx / 25, p = idx - r * 25;
            const float2 v = *reinterpret_cast<const float2*>(sXf + r * DD + 2 * p);
            const __nv_bfloat16 h0 = __float2bfloat16(v.x);
            const __nv_bfloat16 h1 = __float2bfloat16(v.y);
            const __nv_bfloat16 l0 = __float2bfloat16(v.x - __bfloat162float(h0));
            const __nv_bfloat16 l1 = __float2bfloat16(v.y - __bfloat162float(h1));
            const int ks = p >> 3, q = p & 7;
            const int u  = ks * 1024 + r * 8 + (q & 3) * 2 + (q >> 2);
            AhW[u] = (uint32_t)__bfloat16_as_ushort(h0)
                   | ((uint32_t)__bfloat16_as_ushort(h1) << 16);
            AlW[u] = (uint32_t)__bfloat16_as_ushort(l0)
                   | ((uint32_t)__bfloat16_as_ushort(l1) << 16);
        }
        if (tid < TILE_M) {
            sCn[tid] = 0;
            const float* xr = sXf + tid * DD;
            float s = 0.f;
            #pragma unroll
            for (int d = 0; d < DD; ++d) s = __fadd_rn(s, __fmul_rn(xr[d], xr[d]));
            sX2[tid] = s;
        }
        __syncthreads();

        // prefetch next tile (overlaps mma + epilogue)
        {
            const int nt = tile + gridDim.x;
            pref = false;
            if (nt < ntiles) {
                const long long nb = (long long)nt * TILE_M;
                if (nb + TILE_M <= n) {
                    const char* src = reinterpret_cast<const char*>(X + nb * DD);
                    const uint32_t dst = buf ? sx0 : sx1;
                    for (int i = tid; i < TILE_M * DD * 4 / 16; i += TPBT)
                        cp16(dst + i * 16, src + i * 16);
                    pref = true;
                }
            }
            asm volatile("cp.async.commit_group;" ::: "memory");
        }

        // ---- mma: 12 slots (Ah*Bh k0-3, Ah*Bl k0-3, Al*Bh k0-3), 16 n-tiles
        float acc[64];
        #pragma unroll
        for (int i = 0; i < 64; ++i) acc[i] = 0.f;

        #pragma unroll 1
        for (int i = 0; i < 12; ++i) {
            const u64* A = (i < 8) ? Ah64 : Al64;
            const int ks    = i & 3;
            const int bslot = (i < 8) ? i : (i - 8);
            uint32_t a0, a1, a2, a3;
            unpk(A[ks * 512 + arow * 4 + jj],       a0, a2);
            unpk(A[ks * 512 + (arow + 8) * 4 + jj], a1, a3);
            const u64* Bp = Bf + (bslot * CC_TC + half * 128 + rl) * 4 + jj;
            #pragma unroll
            for (int t = 0; t < 16; ++t) {
                uint32_t b0, b1;
                unpk(Bp[t * 32], b0, b1);
                mma16816(acc + t * 4, a0, a1, a2, a3, b0, b1);
            }
        }

        // ---- epilogue
        const int row0 = arow;
        const int row1 = arow + 8;
        const float x20 = sX2[row0];
        const float x21 = sX2[row1];

        float mn0 = FLT_BIG, mn1 = FLT_BIG;
        #pragma unroll
        for (int t = 0; t < 16; ++t) {
            const int c0 = half * 128 + t * 8 + 2 * jj;
            const float p0 = sP2[c0], p1 = sP2[c0 + 1];
            const float s00 = __fsub_rn(__fadd_rn(x20, p0), __fmul_rn(2.f, acc[t*4+0]));
            const float s01 = __fsub_rn(__fadd_rn(x20, p1), __fmul_rn(2.f, acc[t*4+1]));
            const float s10 = __fsub_rn(__fadd_rn(x21, p0), __fmul_rn(2.f, acc[t*4+2]));
            const float s11 = __fsub_rn(__fadd_rn(x21, p1), __fmul_rn(2.f, acc[t*4+3]));
            mn0 = fminf(mn0, fminf(s00, s01));
            mn1 = fminf(mn1, fminf(s10, s11));
        }
        mn0 = fminf(mn0, __shfl_xor_sync(0xFFFFFFFF, mn0, 1));
        mn0 = fminf(mn0, __shfl_xor_sync(0xFFFFFFFF, mn0, 2));
        mn1 = fminf(mn1, __shfl_xor_sync(0xFFFFFFFF, mn1, 1));
        mn1 = fminf(mn1, __shfl_xor_sync(0xFFFFFFFF, mn1, 2));
        if (jj == 0) {
            sPm[row0 * 2 + half] = mn0;
            sPm[row1 * 2 + half] = mn1;
        }
        __syncthreads();
        const float thr0 = fminf(sPm[row0 * 2], sPm[row0 * 2 + 1]) + MARGIN;
        const float thr1 = fminf(sPm[row1 * 2], sPm[row1 * 2 + 1]) + MARGIN;

        #pragma unroll
        for (int t = 0; t < 16; ++t) {
            const int c0 = half * 128 + t * 8 + 2 * jj;
            const float p0 = sP2[c0], p1 = sP2[c0 + 1];
            const float s00 = __fsub_rn(__fadd_rn(x20, p0), __fmul_rn(2.f, acc[t*4+0]));
            const float s01 = __fsub_rn(__fadd_rn(x20, p1), __fmul_rn(2.f, acc[t*4+1]));
            const float s10 = __fsub_rn(__fadd_rn(x21, p0), __fmul_rn(2.f, acc[t*4+2]));
            const float s11 = __fsub_rn(__fadd_rn(x21, p1), __fmul_rn(2.f, acc[t*4+3]));
            if (s00 < thr0) { int p = atomicAdd(&sCn[row0], 1); if (p < 8) sLs[row0*8+p] = c0;     }
            if (s01 < thr0) { int p = atomicAdd(&sCn[row0], 1); if (p < 8) sLs[row0*8+p] = c0 + 1; }
            if (s10 < thr1) { int p = atomicAdd(&sCn[row1], 1); if (p < 8) sLs[row1*8+p] = c0;     }
            if (s11 < thr1) { int p = atomicAdd(&sCn[row1], 1); if (p < 8) sLs[row1*8+p] = c0 + 1; }
        }
        __syncthreads();

        // resolve: even warp of each pair, lane jj==0 (8 rl x 2 rows = 16 rows)
        if (half == 0 && jj == 0) {
            #pragma unroll
            for (int rr = 0; rr < 2; ++rr) {
                const int row = rr ? row1 : row0;
                const float x2 = rr ? x21 : x20;
                const int cnt = sCn[row];
                int pick;
                if (cnt == 1) {
                    pick = sLs[row * 8];     // provably the exact-chain argmin
                } else if (cnt <= 8) {
                    const float* xr = sXf + row * DD;
                    float bs = FLT_BIG; int bc = CC_TC;
                    for (int i = 0; i < cnt; ++i) {
                        const int c = sLs[row * 8 + i];
                        float mm = 0.f;
                        #pragma unroll
                        for (int d = 0; d < DD; ++d)
                            mm = __fmaf_rn(xr[d], __ldg(&Phi[c * DD + d]), mm);
                        const float s = __fsub_rn(__fadd_rn(x2, sP2[c]),
                                                  __fmul_rn(2.f, mm));
                        if (s < bs || (s == bs && c < bc)) { bs = s; bc = c; }
                    }
                    pick = bc;
                } else {                     // truncated list: full exact scan
                    const float* xr = sXf + row * DD;
                    float bs = FLT_BIG; pick = 0;
                    for (int c = 0; c < CC_TC; ++c) {
                        float mm = 0.f;
                        #pragma unroll
                        for (int d = 0; d < DD; ++d)
                            mm = __fmaf_rn(xr[d], __ldg(&Phi[c * DD + d]), mm);
                        const float s = __fsub_rn(__fadd_rn(x2, sP2[c]),
                                                  __fmul_rn(2.f, mm));
                        if (s < bs) { bs = s; pick = c; }
                    }
                }
                if (gbase + row < n) out[gbase + row] = (float)pick;
            }
        }
        buf ^= 1;
    }
}

// --------------------- R6 scalar fallback (D==50, any C) ---------------------
#define TPB   384
#define CHUNK 128
#define PPT   2
#define PTS_PER_BLOCK (TPB * PPT)

__global__ __launch_bounds__(TPB)
void kmeans_fast50(const float* __restrict__ X,
                   const float* __restrict__ Phi,
                   float* __restrict__ out, int n, int C)
{
    __shared__ __align__(16) float sPhiT[DD * CHUNK];
    __shared__ float sP2[CHUNK];

    const int base = blockIdx.x * PTS_PER_BLOCK;
    const int pt0  = base + threadIdx.x;
    const int pt1  = pt0 + TPB;

    float x0[DD], x1[DD];
    {
        const long long r0 = (long long)(pt0 < n ? pt0 : 0) * DD;
        const long long r1 = (long long)(pt1 < n ? pt1 : 0) * DD;
        const float2* a = reinterpret_cast<const float2*>(X + r0);
        const float2* b = reinterpret_cast<const float2*>(X + r1);
        #pragma unroll
        for (int j = 0; j < DD / 2; ++j) {
            float2 va = a[j]; x0[2*j] = va.x; x0[2*j+1] = va.y;
            float2 vb = b[j]; x1[2*j] = vb.x; x1[2*j+1] = vb.y;
        }
    }
    float x2a = 0.f, x2b = 0.f;
    #pragma unroll
    for (int d = 0; d < DD; ++d) {
        x2a = __fadd_rn(x2a, __fmul_rn(x0[d], x0[d]));
        x2b = __fadd_rn(x2b, __fmul_rn(x1[d], x1[d]));
    }

    float best0 = FLT_BIG, best1 = FLT_BIG;
    int   bi0 = 0, bi1 = 0;

    #pragma unroll 1
    for (int cb = 0; cb < C; cb += CHUNK) {
        const int cc = (C - cb < CHUNK) ? (C - cb) : CHUNK;
        __syncthreads();
        for (int i = threadIdx.x; i < cc * DD; i += TPB) {
            const int c = i / DD, d = i - c * DD;
            sPhiT[d * CHUNK + c] = Phi[(long long)(cb + c) * DD + d];
        }
        __syncthreads();
        if (threadIdx.x < cc) {
            float s = 0.f;
            #pragma unroll
            for (int d = 0; d < DD; ++d) {
                const float v = sPhiT[d * CHUNK + threadIdx.x];
                s = __fadd_rn(s, __fmul_rn(v, v));
            }
            sP2[threadIdx.x] = s;
        }
        __syncthreads();

        int c = 0;
        #pragma unroll 1
        for (; c + 4 <= cc; c += 4) {
            float a00=0.f,a01=0.f,a02=0.f,a03=0.f,a10=0.f,a11=0.f,a12=0.f,a13=0.f;
            const float4* pT = reinterpret_cast<const float4*>(sPhiT + c);
            #pragma unroll
            for (int d = 0; d < DD; ++d) {
                const float4 p = pT[d * (CHUNK / 4)];
                a00 = __fmaf_rn(x0[d], p.x, a00);
                a01 = __fmaf_rn(x0[d], p.y, a01);
                a02 = __fmaf_rn(x0[d], p.z, a02);
                a03 = __fmaf_rn(x0[d], p.w, a03);
                a10 = __fmaf_rn(x1[d], p.x, a10);
                a11 = __fmaf_rn(x1[d], p.y, a11);
                a12 = __fmaf_rn(x1[d], p.z, a12);
                a13 = __fmaf_rn(x1[d], p.w, a13);
            }
            const float q0=sP2[c],q1=sP2[c+1],q2=sP2[c+2],q3=sP2[c+3];
            const float s00=__fsub_rn(__fadd_rn(x2a,q0),__fmul_rn(2.f,a00));
            const float s01=__fsub_rn(__fadd_rn(x2a,q1),__fmul_rn(2.f,a01));
            const float s02=__fsub_rn(__fadd_rn(x2a,q2),__fmul_rn(2.f,a02));
            const float s03=__fsub_rn(__fadd_rn(x2a,q3),__fmul_rn(2.f,a03));
            const float s10=__fsub_rn(__fadd_rn(x2b,q0),__fmul_rn(2.f,a10));
            const float s11=__fsub_rn(__fadd_rn(x2b,q1),__fmul_rn(2.f,a11));
            const float s12=__fsub_rn(__fadd_rn(x2b,q2),__fmul_rn(2.f,a12));
            const float s13=__fsub_rn(__fadd_rn(x2b,q3),__fmul_rn(2.f,a13));
            const int g = cb + c;
            if (s00<best0){best0=s00;bi0=g;}   if (s01<best0){best0=s01;bi0=g+1;}
            if (s02<best0){best0=s02;bi0=g+2;} if (s03<best0){best0=s03;bi0=g+3;}
            if (s10<best1){best1=s10;bi1=g;}   if (s11<best1){best1=s11;bi1=g+1;}
            if (s12<best1){best1=s12;bi1=g+2;} if (s13<best1){best1=s13;bi1=g+3;}
        }
        for (; c < cc; ++c) {
            float a0=0.f,a1=0.f;
            #pragma unroll
            for (int d = 0; d < DD; ++d) {
                const float p = sPhiT[d * CHUNK + c];
                a0=__fmaf_rn(x0[d],p,a0); a1=__fmaf_rn(x1[d],p,a1);
            }
            const float q = sP2[c];
            const float s0=__fsub_rn(__fadd_rn(x2a,q),__fmul_rn(2.f,a0));
            const float s1=__fsub_rn(__fadd_rn(x2b,q),__fmul_rn(2.f,a1));
            if (s0<best0){best0=s0;bi0=cb+c;}
            if (s1<best1){best1=s1;bi1=cb+c;}
        }
    }
    if (pt0 < n) out[pt0] = (float)bi0;
    if (pt1 < n) out[pt1] = (float)bi1;
}

// --------------------- generic fallback: any D, C ---------------------
__global__ __launch_bounds__(256)
void kmeans_generic(const float* __restrict__ X,
                    const float* __restrict__ Phi,
                    float* __restrict__ out, int n, int D, int C)
{
    for (int idx = blockIdx.x * blockDim.x + threadIdx.x; idx < n;
         idx += gridDim.x * blockDim.x) {
        float xr[MAXD];
        const int Dc = (D < MAXD) ? D : MAXD;
        const long long row = (long long)idx * D;
        for (int d = 0; d < Dc; ++d) xr[d] = X[row + d];
        float x2 = 0.f;
        for (int d = 0; d < Dc; ++d) x2 = __fadd_rn(x2, __fmul_rn(xr[d], xr[d]));
        float best = FLT_BIG; int bi = 0;
        for (int c = 0; c < C; ++c) {
            const long long pr = (long long)c * D;
            float mm = 0.f, p2 = 0.f;
            for (int d = 0; d < Dc; ++d) {
                const float pv = __ldg(&Phi[pr + d]);
                mm = __fmaf_rn(xr[d], pv, mm);
                p2 = __fadd_rn(p2, __fmul_rn(pv, pv));
            }
            const float s = __fsub_rn(__fadd_rn(x2, p2), __fmul_rn(2.f, mm));
            if (s < best) { best = s; bi = c; }
        }
        out[idx] = (float)bi;
    }
}

// ------------------------------ launch ------------------------------
extern "C" void kernel_launch(void* const* d_in, const int* in_sizes, int n_in,
                              void* d_out, int out_size)
{
    int iX = 0;
    for (int i = 1; i < n_in; ++i)
        if (in_sizes[i] > in_sizes[iX]) iX = i;
    int iP = (iX == 0) ? (n_in > 1 ? 1 : 0) : 0;
    for (int i = 0; i < n_in; ++i)
        if (i != iX && in_sizes[i] > in_sizes[iP]) iP = i;

    const float* X   = (const float*)d_in[iX];
    const float* Phi = (const float*)d_in[iP];
    float*       out = (float*)d_out;

    const int n = out_size;
    if (n <= 0) return;
    const int D = in_sizes[iX] / n;
    const int C = (D > 0) ? in_sizes[iP] / D : 0;
    if (D <= 0 || C <= 0) return;

    if (D == DD && C == CC_TC) {
        prep_kernel<<<1, 256>>>(Phi);
        cudaFuncSetAttribute(kmeans_tc,
                             cudaFuncAttributeMaxDynamicSharedMemorySize, SM_TOT);
        const int ntiles = (n + TILE_M - 1) / TILE_M;
        const int grid = (ntiles < NSM) ? ntiles : NSM;
        kmeans_tc<<<grid, TPBT, SM_TOT>>>(X, Phi, out, n, ntiles);
    } else if (D == DD) {
        const int blocks = (n + PTS_PER_BLOCK - 1) / PTS_PER_BLOCK;
        kmeans_fast50<<<blocks, TPB>>>(X, Phi, out, n, C);
    } else {
        int blocks = (n + 255) / 256;
        if (blocks > 65535 * 8) blocks = 65535 * 8;
        kmeans_generic<<<blocks, 256>>>(X, Phi, out, n, D, C);
    }
}